// round 12
// baseline (speedup 1.0000x reference)
#include <cuda_runtime.h>
#include <math.h>

#define BB 16
#define CC 256
#define TT 4096
#define KK 5

#define WIN  166
#define WOFF 16

// fp32 -> tf32 RNE rounding (bit-exact round-to-nearest-even on low 13 bits)
__device__ __forceinline__ float tf32r(float x) {
    unsigned int u = __float_as_uint(x);
    u += 0xFFFu + ((u >> 13) & 1u);
    u &= ~0x1FFFu;
    return __uint_as_float(u);
}

// ===========================================================================
// Precomputed B fragments (hi part only) for mma.m16n8k8.row.col tf32.
// g_wfrag[(((kc*2 + wn)*8 + nt)*32 + lane)*2 + r]
// b_r = tf32r(W[n = wn*64+nt*8+(lane>>2)][k = kc*8+(lane&3)+r*4])
// ===========================================================================
__device__ __align__(16) float g_wfrag[96 * 2 * 8 * 32 * 2];

__global__ void prep_wfrag(const float* __restrict__ rp1_w) {
    int e = blockIdx.x * blockDim.x + threadIdx.x;
    if (e >= 96 * 2 * 8 * 32 * 2) return;
    int r2   = e & 1;
    int lane = (e >> 1) & 31;
    int nt   = (e >> 6) & 7;
    int wn   = (e >> 9) & 1;
    int kc   = (e >> 10);
    int tig = lane & 3;
    int g   = lane >> 2;
    int k = kc * 8 + tig + r2 * 4;
    int c = k / 3;
    int d = k - 3 * c;
    int n = wn * 64 + nt * 8 + g;
    g_wfrag[e] = tf32r(__ldg(rp1_w + (n * CC + c) * 3 + d));
}

// m16n8k8 tf32 mma (family-portable PTX)
__device__ __forceinline__ void mma8(float* d, const unsigned* a, unsigned b0, unsigned b1) {
    asm volatile(
        "mma.sync.aligned.m16n8k8.row.col.f32.tf32.tf32.f32 "
        "{%0,%1,%2,%3},{%4,%5,%6,%7},{%8,%9},{%0,%1,%2,%3};"
        : "+f"(d[0]), "+f"(d[1]), "+f"(d[2]), "+f"(d[3])
        : "r"(a[0]), "r"(a[1]), "r"(a[2]), "r"(a[3]), "r"(b0), "r"(b1));
}

// ===========================================================================
// Kernel 1: round-7 k_deform, staging loops float4-vectorized (staged values
// and all compute numerics bit-identical; interior blocks take the fast path).
// ===========================================================================
#define DEF_SMEM_FLOATS (CC * 30 + CC * KK + 32 * WIN)

__device__ __forceinline__ void stage_chunk(
    float* s_b, const float* xb, int cc, int t0, int tid, bool interior)
{
    if (interior) {
        #pragma unroll 1
        for (int idx = tid; idx < 32 * 42; idx += 128) {
            int ci = idx / 42;
            int q = idx - ci * 42;
            const float* row = xb + (size_t)(cc + ci) * TT + (t0 - WOFF);
            float* dst = s_b + ci * WIN;
            if (q < 41) {
                float4 v = __ldg(reinterpret_cast<const float4*>(row) + q);
                dst[q * 4 + 0] = v.x;
                dst[q * 4 + 1] = v.y;
                dst[q * 4 + 2] = v.z;
                dst[q * 4 + 3] = v.w;
            } else {
                dst[164] = __ldg(row + 164);
                dst[165] = __ldg(row + 165);
            }
        }
    } else {
        #pragma unroll 1
        for (int idx = tid; idx < 32 * WIN; idx += 128) {
            int ci = idx / WIN;
            int u = idx - ci * WIN;
            int tg = t0 - WOFF + u;
            s_b[idx] = (tg >= 0 && tg < TT) ? __ldg(xb + (size_t)(cc + ci) * TT + tg) : 0.f;
        }
    }
}

__global__ __launch_bounds__(128) void k_deform(
    const float* __restrict__ x,
    const float* __restrict__ ow, const float* __restrict__ ob,
    const float* __restrict__ mw, const float* __restrict__ mb,
    const float* __restrict__ weight,
    float* __restrict__ deformed)
{
    extern __shared__ float dsm_d[];
    float* s_w  = dsm_d;
    float* s_dw = dsm_d + CC * 30;
    float* s_b  = dsm_d + CC * 30 + CC * KK;

    const int tid = threadIdx.x;
    const int t0 = blockIdx.x * 128;
    const int b = blockIdx.y;
    const float* xb = x + (size_t)b * CC * TT;
    const bool interior = (t0 >= WOFF) && (t0 - WOFF + WIN <= TT);

    for (int i = tid; i < CC * 30; i += 128) {
        int c = i / 30;
        int j = i - c * 30;
        float v;
        if (j < 15) {
            int k = j / 3, d = j - k * 3;
            v = ow[k * (CC * 3) + c * 3 + d];
        } else {
            int jj = j - 15;
            int k = jj / 3, d = jj - k * 3;
            v = mw[k * (CC * 3) + c * 3 + d];
        }
        s_w[i] = v;
    }

    float offa[KK] = {0.f, 0.f, 0.f, 0.f, 0.f};
    float moda[KK] = {0.f, 0.f, 0.f, 0.f, 0.f};

    for (int cc = 0; cc < CC; cc += 32) {
        __syncthreads();
        stage_chunk(s_b, xb, cc, t0, tid, interior);
        __syncthreads();
        float offc[KK] = {0.f, 0.f, 0.f, 0.f, 0.f};
        float modc[KK] = {0.f, 0.f, 0.f, 0.f, 0.f};
        #pragma unroll 1
        for (int ci = 0; ci < 32; ci++) {
            const float* wrow = s_w + (cc + ci) * 30;
            const float* xs = s_b + ci * WIN + tid + (WOFF - 1);
            float x0 = xs[0];
            float x1 = xs[1];
            float x2 = xs[2];
            #pragma unroll
            for (int k = 0; k < KK; k++) {
                offc[k] += x0 * wrow[k * 3 + 0] + x1 * wrow[k * 3 + 1] + x2 * wrow[k * 3 + 2];
                modc[k] += x0 * wrow[15 + k * 3 + 0] + x1 * wrow[15 + k * 3 + 1] + x2 * wrow[15 + k * 3 + 2];
            }
        }
        #pragma unroll
        for (int k = 0; k < KK; k++) { offa[k] += offc[k]; moda[k] += modc[k]; }
    }

    const int t = t0 + tid;
    float mf[KK], mc[KK];
    int pfi[KK], pci[KK];
    #pragma unroll
    for (int k = 0; k < KK; k++) {
        float off = offa[k] + __ldg(ob + k);
        float z = moda[k] + __ldg(mb + k);
        float mod = 1.f / (1.f + expf(-z));
        float pos = (float)(t + k - 2) + off;
        pos = fminf(fmaxf(pos, 0.f), (float)(TT - 1));
        float pf = floorf(pos);
        float pc = ceilf(pos);
        mf[k] = (pc - pos) * mod;
        mc[k] = (pos - pf) * mod;
        pfi[k] = (int)pf;
        pci[k] = (int)pc;
    }

    int idxf[KK], idxc[KK];
    bool allin = true;
    #pragma unroll
    for (int k = 0; k < KK; k++) {
        idxf[k] = pfi[k] - (t0 - WOFF);
        idxc[k] = pci[k] - (t0 - WOFF);
        allin = allin && ((unsigned)idxf[k] < (unsigned)WIN) && ((unsigned)idxc[k] < (unsigned)WIN);
    }
    const bool fast = __all_sync(0xffffffffu, allin);

    __syncthreads();
    for (int i = tid; i < CC * KK; i += 128) {
        int c = i / KK;
        int k = i - c * KK;
        s_dw[i] = __ldg(weight + ((size_t)c * CC + c) * KK + k);
    }

    float* db = deformed + (size_t)b * CC * TT;
    for (int cc = 0; cc < CC; cc += 32) {
        __syncthreads();
        stage_chunk(s_b, xb, cc, t0, tid, interior);
        __syncthreads();
        if (fast) {
            #pragma unroll 2
            for (int ci = 0; ci < 32; ci++) {
                const float* xs = s_b + ci * WIN;
                const float* dwc = s_dw + (cc + ci) * KK;
                float acc = 0.f;
                #pragma unroll
                for (int k = 0; k < KK; k++) {
                    float s = xs[idxf[k]] * mf[k] + xs[idxc[k]] * mc[k];
                    acc = fmaf(s, dwc[k], acc);
                }
                db[(size_t)(cc + ci) * TT + t] = acc;
            }
        } else {
            #pragma unroll 1
            for (int ci = 0; ci < 32; ci++) {
                const float* xc = xb + (size_t)(cc + ci) * TT;
                const float* dwc = s_dw + (cc + ci) * KK;
                float acc = 0.f;
                #pragma unroll
                for (int k = 0; k < KK; k++) {
                    float s = __ldg(xc + pfi[k]) * mf[k] + __ldg(xc + pci[k]) * mc[k];
                    acc = fmaf(s, dwc[k], acc);
                }
                db[(size_t)(cc + ci) * TT + t] = acc;
            }
        }
    }
}

// ===========================================================================
// Kernel 2: rp1 conv as mma.sync GEMM, A split hi/lo, B hi-only (2 MMAs per
// tile instead of 3; h = a * b_hi, error ~6e-5 relative on recovery only).
// CTA: 256 threads = 128 t x 128 c2; grid 512.
// ===========================================================================
__global__ __launch_bounds__(256, 2) void k_recover2(
    const float* __restrict__ deformed,
    const float* __restrict__ rp1_b,
    const float* __restrict__ rp2_w,
    const float* __restrict__ rp2_b,
    float* __restrict__ recovery)
{
    __shared__ float sdef[64 * 132];
    __shared__ float sp[2][128];

    const int tid = threadIdx.x;
    const int wid = tid >> 5;
    const int lane = tid & 31;
    const int wm = wid & 3;
    const int wn = wid >> 2;
    const int tig = lane & 3;
    const int g = lane >> 2;

    const int bx = blockIdx.x;
    const int b  = bx >> 5;
    const int t0 = (bx & 31) << 7;
    const float* db = deformed + (size_t)b * CC * TT;
    const uint2* Wf = reinterpret_cast<const uint2*>(g_wfrag);

    float dacc[2][8][4];
    #pragma unroll
    for (int mt = 0; mt < 2; mt++)
        #pragma unroll
        for (int nt = 0; nt < 8; nt++)
            #pragma unroll
            for (int r = 0; r < 4; r++) dacc[mt][nt][r] = 0.f;

    const int ttb = wm * 32 + g;

    for (int cg = 0; cg < 4; cg++) {
        __syncthreads();
        for (int i = tid; i < 64 * 130; i += 256) {
            int j = i / 130;
            int u = i - j * 130;
            int tg = t0 - 1 + u;
            sdef[j * 132 + u] = (tg >= 0 && tg < TT)
                ? __ldg(db + (size_t)(cg * 64 + j) * TT + tg) : 0.f;
        }
        __syncthreads();

        #pragma unroll 1
        for (int kcl = 0; kcl < 24; kcl++) {
            const int kc = cg * 24 + kcl;
            const int kk0 = kc * 8 + tig;
            const int kk1 = kk0 + 4;
            const int c0 = kk0 / 3, d0 = kk0 - 3 * c0, j0 = c0 - cg * 64;
            const int c1 = kk1 / 3, d1 = kk1 - 3 * c1, j1 = c1 - cg * 64;

            unsigned ahi[2][4], alo[2][4];
            #pragma unroll
            for (int mt = 0; mt < 2; mt++) {
                const int tt = ttb + mt * 16;
                float v0 = sdef[j0 * 132 + tt + d0];
                float v1 = sdef[j0 * 132 + tt + 8 + d0];
                float v2 = sdef[j1 * 132 + tt + d1];
                float v3 = sdef[j1 * 132 + tt + 8 + d1];
                float h0 = tf32r(v0), h1 = tf32r(v1), h2 = tf32r(v2), h3 = tf32r(v3);
                ahi[mt][0] = __float_as_uint(h0);
                ahi[mt][1] = __float_as_uint(h1);
                ahi[mt][2] = __float_as_uint(h2);
                ahi[mt][3] = __float_as_uint(h3);
                alo[mt][0] = __float_as_uint(tf32r(v0 - h0));
                alo[mt][1] = __float_as_uint(tf32r(v1 - h1));
                alo[mt][2] = __float_as_uint(tf32r(v2 - h2));
                alo[mt][3] = __float_as_uint(tf32r(v3 - h3));
            }

            const int fb = ((kc * 2 + wn) * 8) * 32 + lane;
            #pragma unroll
            for (int nt = 0; nt < 8; nt++) {
                uint2 bh = __ldg(Wf + fb + nt * 32);
                #pragma unroll
                for (int mt = 0; mt < 2; mt++) {
                    mma8(dacc[mt][nt], ahi[mt], bh.x, bh.y);
                    mma8(dacc[mt][nt], alo[mt], bh.x, bh.y);
                }
            }
        }
    }

    #pragma unroll
    for (int mt = 0; mt < 2; mt++) {
        float s0 = 0.f, s8 = 0.f;
        #pragma unroll
        for (int nt = 0; nt < 8; nt++) {
            int c2 = wn * 64 + nt * 8 + tig * 2;
            float b1a = __ldg(rp1_b + c2),     b1b = __ldg(rp1_b + c2 + 1);
            float w2a = __ldg(rp2_w + c2),     w2b = __ldg(rp2_w + c2 + 1);
            s0 += fmaxf(dacc[mt][nt][0] + b1a, 0.f) * w2a
                + fmaxf(dacc[mt][nt][1] + b1b, 0.f) * w2b;
            s8 += fmaxf(dacc[mt][nt][2] + b1a, 0.f) * w2a
                + fmaxf(dacc[mt][nt][3] + b1b, 0.f) * w2b;
        }
        s0 += __shfl_xor_sync(0xffffffffu, s0, 1);
        s0 += __shfl_xor_sync(0xffffffffu, s0, 2);
        s8 += __shfl_xor_sync(0xffffffffu, s8, 1);
        s8 += __shfl_xor_sync(0xffffffffu, s8, 2);
        if (tig == 0) {
            sp[wn][wm * 32 + mt * 16 + g] = s0;
            sp[wn][wm * 32 + mt * 16 + g + 8] = s8;
        }
    }
    __syncthreads();

    if (tid < 128) {
        recovery[(size_t)b * TT + t0 + tid] = sp[0][tid] + sp[1][tid] + __ldg(rp2_b);
    }
}

// ---------------------------------------------------------------------------
extern "C" void kernel_launch(void* const* d_in, const int* in_sizes, int n_in,
                              void* d_out, int out_size) {
    const float* x     = (const float*)d_in[0];
    const float* ow    = (const float*)d_in[1];
    const float* ob    = (const float*)d_in[2];
    const float* mw    = (const float*)d_in[3];
    const float* mb    = (const float*)d_in[4];
    const float* wgt   = (const float*)d_in[5];
    const float* rp1_w = (const float*)d_in[6];
    const float* rp1_b = (const float*)d_in[7];
    const float* rp2_w = (const float*)d_in[8];
    const float* rp2_b = (const float*)d_in[9];

    float* out = (float*)d_out;
    float* deformed = out;                              // (B, C, T)
    float* recovery = out + (size_t)BB * CC * TT;       // (B, T)

    cudaFuncSetAttribute(k_deform, cudaFuncAttributeMaxDynamicSharedMemorySize,
                         DEF_SMEM_FLOATS * (int)sizeof(float));

    prep_wfrag<<<(96 * 2 * 8 * 32 * 2 + 255) / 256, 256>>>(rp1_w);
    k_deform<<<dim3(TT / 128, BB), 128, DEF_SMEM_FLOATS * sizeof(float)>>>(
        x, ow, ob, mw, mb, wgt, deformed);
    k_recover2<<<512, 256>>>(deformed, rp1_b, rp2_w, rp2_b, recovery);
}

// round 13
// speedup vs baseline: 1.1789x; 1.1789x over previous
#include <cuda_runtime.h>
#include <math.h>

#define BB 16
#define CC 256
#define TT 4096
#define KK 5

#define WIN  166
#define WOFF 16

// fp32 -> tf32 RNE rounding (bit-exact round-to-nearest-even on low 13 bits)
__device__ __forceinline__ float tf32r(float x) {
    unsigned int u = __float_as_uint(x);
    u += 0xFFFu + ((u >> 13) & 1u);
    u &= ~0x1FFFu;
    return __uint_as_float(u);
}

// ===========================================================================
// Precomputed B fragments (hi and lo parts) for mma.m16n8k8.row.col tf32.
// g_wfrag[((((p*96 + kc)*2 + wn)*8 + nt)*32 + lane)*2 + r]
// b_r = part_p(W[n = wn*64+nt*8+(lane>>2)][k = kc*8+(lane&3)+r*4])
// ===========================================================================
__device__ __align__(16) float g_wfrag[2 * 96 * 2 * 8 * 32 * 2];

__global__ void prep_wfrag(const float* __restrict__ rp1_w) {
    int e = blockIdx.x * blockDim.x + threadIdx.x;
    if (e >= 2 * 96 * 2 * 8 * 32 * 2) return;
    int r2   = e & 1;
    int lane = (e >> 1) & 31;
    int nt   = (e >> 6) & 7;
    int wn   = (e >> 9) & 1;
    int kc   = (e >> 10) % 96;
    int p    = (e >> 10) / 96;
    int tig = lane & 3;
    int g   = lane >> 2;
    int k = kc * 8 + tig + r2 * 4;
    int c = k / 3;
    int d = k - 3 * c;
    int n = wn * 64 + nt * 8 + g;
    float w = __ldg(rp1_w + (n * CC + c) * 3 + d);
    float hi = tf32r(w);
    g_wfrag[e] = p ? tf32r(w - hi) : hi;
}

// m16n8k8 tf32 mma (family-portable PTX)
__device__ __forceinline__ void mma8(float* d, const unsigned* a, unsigned b0, unsigned b1) {
    asm volatile(
        "mma.sync.aligned.m16n8k8.row.col.f32.tf32.tf32.f32 "
        "{%0,%1,%2,%3},{%4,%5,%6,%7},{%8,%9},{%0,%1,%2,%3};"
        : "+f"(d[0]), "+f"(d[1]), "+f"(d[2]), "+f"(d[3])
        : "r"(a[0]), "r"(a[1]), "r"(a[2]), "r"(a[3]), "r"(b0), "r"(b1));
}

// ===========================================================================
// Kernel 1: round-7 k_deform VERBATIM (176.3us measured; scalar staging —
// every vectorization attempt has regressed it; numerics frozen)
// ===========================================================================
#define DEF_SMEM_FLOATS (CC * 30 + CC * KK + 32 * WIN)

__global__ __launch_bounds__(128) void k_deform(
    const float* __restrict__ x,
    const float* __restrict__ ow, const float* __restrict__ ob,
    const float* __restrict__ mw, const float* __restrict__ mb,
    const float* __restrict__ weight,
    float* __restrict__ deformed)
{
    extern __shared__ float dsm_d[];
    float* s_w  = dsm_d;
    float* s_dw = dsm_d + CC * 30;
    float* s_b  = dsm_d + CC * 30 + CC * KK;

    const int tid = threadIdx.x;
    const int t0 = blockIdx.x * 128;
    const int b = blockIdx.y;
    const float* xb = x + (size_t)b * CC * TT;

    for (int i = tid; i < CC * 30; i += 128) {
        int c = i / 30;
        int j = i - c * 30;
        float v;
        if (j < 15) {
            int k = j / 3, d = j - k * 3;
            v = ow[k * (CC * 3) + c * 3 + d];
        } else {
            int jj = j - 15;
            int k = jj / 3, d = jj - k * 3;
            v = mw[k * (CC * 3) + c * 3 + d];
        }
        s_w[i] = v;
    }

    float offa[KK] = {0.f, 0.f, 0.f, 0.f, 0.f};
    float moda[KK] = {0.f, 0.f, 0.f, 0.f, 0.f};

    for (int cc = 0; cc < CC; cc += 32) {
        __syncthreads();
        for (int idx = tid; idx < 32 * WIN; idx += 128) {
            int ci = idx / WIN;
            int u = idx - ci * WIN;
            int tg = t0 - WOFF + u;
            s_b[idx] = (tg >= 0 && tg < TT) ? __ldg(xb + (size_t)(cc + ci) * TT + tg) : 0.f;
        }
        __syncthreads();
        float offc[KK] = {0.f, 0.f, 0.f, 0.f, 0.f};
        float modc[KK] = {0.f, 0.f, 0.f, 0.f, 0.f};
        #pragma unroll 1
        for (int ci = 0; ci < 32; ci++) {
            const float* wrow = s_w + (cc + ci) * 30;
            const float* xs = s_b + ci * WIN + tid + (WOFF - 1);
            float x0 = xs[0];
            float x1 = xs[1];
            float x2 = xs[2];
            #pragma unroll
            for (int k = 0; k < KK; k++) {
                offc[k] += x0 * wrow[k * 3 + 0] + x1 * wrow[k * 3 + 1] + x2 * wrow[k * 3 + 2];
                modc[k] += x0 * wrow[15 + k * 3 + 0] + x1 * wrow[15 + k * 3 + 1] + x2 * wrow[15 + k * 3 + 2];
            }
        }
        #pragma unroll
        for (int k = 0; k < KK; k++) { offa[k] += offc[k]; moda[k] += modc[k]; }
    }

    const int t = t0 + tid;
    float mf[KK], mc[KK];
    int pfi[KK], pci[KK];
    #pragma unroll
    for (int k = 0; k < KK; k++) {
        float off = offa[k] + __ldg(ob + k);
        float z = moda[k] + __ldg(mb + k);
        float mod = 1.f / (1.f + expf(-z));
        float pos = (float)(t + k - 2) + off;
        pos = fminf(fmaxf(pos, 0.f), (float)(TT - 1));
        float pf = floorf(pos);
        float pc = ceilf(pos);
        mf[k] = (pc - pos) * mod;
        mc[k] = (pos - pf) * mod;
        pfi[k] = (int)pf;
        pci[k] = (int)pc;
    }

    int idxf[KK], idxc[KK];
    bool allin = true;
    #pragma unroll
    for (int k = 0; k < KK; k++) {
        idxf[k] = pfi[k] - (t0 - WOFF);
        idxc[k] = pci[k] - (t0 - WOFF);
        allin = allin && ((unsigned)idxf[k] < (unsigned)WIN) && ((unsigned)idxc[k] < (unsigned)WIN);
    }
    const bool fast = __all_sync(0xffffffffu, allin);

    __syncthreads();
    for (int i = tid; i < CC * KK; i += 128) {
        int c = i / KK;
        int k = i - c * KK;
        s_dw[i] = __ldg(weight + ((size_t)c * CC + c) * KK + k);
    }

    float* db = deformed + (size_t)b * CC * TT;
    for (int cc = 0; cc < CC; cc += 32) {
        __syncthreads();
        for (int idx = tid; idx < 32 * WIN; idx += 128) {
            int ci = idx / WIN;
            int u = idx - ci * WIN;
            int tg = t0 - WOFF + u;
            s_b[idx] = (tg >= 0 && tg < TT) ? __ldg(xb + (size_t)(cc + ci) * TT + tg) : 0.f;
        }
        __syncthreads();
        if (fast) {
            #pragma unroll 2
            for (int ci = 0; ci < 32; ci++) {
                const float* xs = s_b + ci * WIN;
                const float* dwc = s_dw + (cc + ci) * KK;
                float acc = 0.f;
                #pragma unroll
                for (int k = 0; k < KK; k++) {
                    float s = xs[idxf[k]] * mf[k] + xs[idxc[k]] * mc[k];
                    acc = fmaf(s, dwc[k], acc);
                }
                db[(size_t)(cc + ci) * TT + t] = acc;
            }
        } else {
            #pragma unroll 1
            for (int ci = 0; ci < 32; ci++) {
                const float* xc = xb + (size_t)(cc + ci) * TT;
                const float* dwc = s_dw + (cc + ci) * KK;
                float acc = 0.f;
                #pragma unroll
                for (int k = 0; k < KK; k++) {
                    float s = __ldg(xc + pfi[k]) * mf[k] + __ldg(xc + pci[k]) * mc[k];
                    acc = fmaf(s, dwc[k], acc);
                }
                db[(size_t)(cc + ci) * TT + t] = acc;
            }
        }
    }
}

// ===========================================================================
// Kernel 2: 3xTF32 mma.sync GEMM (round-11 numerics), A PRE-SPLIT into smem
// hi/lo at staging time (removes the in-loop split ALU chain), k-chunk loop
// unroll 2 for cross-iteration latency hiding.
// CTA: 256 threads = 128 t x 128 c2; grid 512; dyn smem 2*64*132 floats.
// ===========================================================================
#define REC_SMEM_FLOATS (2 * 64 * 132)

__global__ __launch_bounds__(256, 2) void k_recover2(
    const float* __restrict__ deformed,
    const float* __restrict__ rp1_b,
    const float* __restrict__ rp2_w,
    const float* __restrict__ rp2_b,
    float* __restrict__ recovery)
{
    extern __shared__ float dsm_r[];
    float* shi = dsm_r;              // [j][u] hi part, stride 132
    float* slo = dsm_r + 64 * 132;   // [j][u] lo part
    __shared__ float sp[2][128];

    const int tid = threadIdx.x;
    const int wid = tid >> 5;
    const int lane = tid & 31;
    const int wm = wid & 3;
    const int wn = wid >> 2;
    const int tig = lane & 3;
    const int g = lane >> 2;

    const int bx = blockIdx.x;
    const int b  = bx >> 5;
    const int t0 = (bx & 31) << 7;
    const float* db = deformed + (size_t)b * CC * TT;
    const uint2* Wf = reinterpret_cast<const uint2*>(g_wfrag);

    float dacc[2][8][4];
    #pragma unroll
    for (int mt = 0; mt < 2; mt++)
        #pragma unroll
        for (int nt = 0; nt < 8; nt++)
            #pragma unroll
            for (int r = 0; r < 4; r++) dacc[mt][nt][r] = 0.f;

    const int ttb = wm * 32 + g;

    for (int cg = 0; cg < 4; cg++) {
        __syncthreads();
        for (int i = tid; i < 64 * 130; i += 256) {
            int j = i / 130;
            int u = i - j * 130;
            int tg = t0 - 1 + u;
            float v = (tg >= 0 && tg < TT)
                ? __ldg(db + (size_t)(cg * 64 + j) * TT + tg) : 0.f;
            float hi = tf32r(v);
            shi[j * 132 + u] = hi;
            slo[j * 132 + u] = tf32r(v - hi);
        }
        __syncthreads();

        #pragma unroll 2
        for (int kcl = 0; kcl < 24; kcl++) {
            const int kc = cg * 24 + kcl;
            const int kk0 = kc * 8 + tig;
            const int kk1 = kk0 + 4;
            const int c0 = kk0 / 3, d0 = kk0 - 3 * c0, j0 = c0 - cg * 64;
            const int c1 = kk1 / 3, d1 = kk1 - 3 * c1, j1 = c1 - cg * 64;

            unsigned ahi[2][4], alo[2][4];
            #pragma unroll
            for (int mt = 0; mt < 2; mt++) {
                const int tt = ttb + mt * 16;
                const int o0 = j0 * 132 + tt + d0;
                const int o1 = j1 * 132 + tt + d1;
                ahi[mt][0] = __float_as_uint(shi[o0]);
                ahi[mt][1] = __float_as_uint(shi[o0 + 8]);
                ahi[mt][2] = __float_as_uint(shi[o1]);
                ahi[mt][3] = __float_as_uint(shi[o1 + 8]);
                alo[mt][0] = __float_as_uint(slo[o0]);
                alo[mt][1] = __float_as_uint(slo[o0 + 8]);
                alo[mt][2] = __float_as_uint(slo[o1]);
                alo[mt][3] = __float_as_uint(slo[o1 + 8]);
            }

            const int fb = ((kc * 2 + wn) * 8) * 32 + lane;        // hi base
            const int fl = (((96 + kc) * 2 + wn) * 8) * 32 + lane; // lo base
            #pragma unroll
            for (int nt = 0; nt < 8; nt++) {
                uint2 bh = __ldg(Wf + fb + nt * 32);
                uint2 bl = __ldg(Wf + fl + nt * 32);
                #pragma unroll
                for (int mt = 0; mt < 2; mt++) {
                    mma8(dacc[mt][nt], ahi[mt], bh.x, bh.y);
                    mma8(dacc[mt][nt], ahi[mt], bl.x, bl.y);
                    mma8(dacc[mt][nt], alo[mt], bh.x, bh.y);
                }
            }
        }
    }

    #pragma unroll
    for (int mt = 0; mt < 2; mt++) {
        float s0 = 0.f, s8 = 0.f;
        #pragma unroll
        for (int nt = 0; nt < 8; nt++) {
            int c2 = wn * 64 + nt * 8 + tig * 2;
            float b1a = __ldg(rp1_b + c2),     b1b = __ldg(rp1_b + c2 + 1);
            float w2a = __ldg(rp2_w + c2),     w2b = __ldg(rp2_w + c2 + 1);
            s0 += fmaxf(dacc[mt][nt][0] + b1a, 0.f) * w2a
                + fmaxf(dacc[mt][nt][1] + b1b, 0.f) * w2b;
            s8 += fmaxf(dacc[mt][nt][2] + b1a, 0.f) * w2a
                + fmaxf(dacc[mt][nt][3] + b1b, 0.f) * w2b;
        }
        s0 += __shfl_xor_sync(0xffffffffu, s0, 1);
        s0 += __shfl_xor_sync(0xffffffffu, s0, 2);
        s8 += __shfl_xor_sync(0xffffffffu, s8, 1);
        s8 += __shfl_xor_sync(0xffffffffu, s8, 2);
        if (tig == 0) {
            sp[wn][wm * 32 + mt * 16 + g] = s0;
            sp[wn][wm * 32 + mt * 16 + g + 8] = s8;
        }
    }
    __syncthreads();

    if (tid < 128) {
        recovery[(size_t)b * TT + t0 + tid] = sp[0][tid] + sp[1][tid] + __ldg(rp2_b);
    }
}

// ---------------------------------------------------------------------------
extern "C" void kernel_launch(void* const* d_in, const int* in_sizes, int n_in,
                              void* d_out, int out_size) {
    const float* x     = (const float*)d_in[0];
    const float* ow    = (const float*)d_in[1];
    const float* ob    = (const float*)d_in[2];
    const float* mw    = (const float*)d_in[3];
    const float* mb    = (const float*)d_in[4];
    const float* wgt   = (const float*)d_in[5];
    const float* rp1_w = (const float*)d_in[6];
    const float* rp1_b = (const float*)d_in[7];
    const float* rp2_w = (const float*)d_in[8];
    const float* rp2_b = (const float*)d_in[9];

    float* out = (float*)d_out;
    float* deformed = out;                              // (B, C, T)
    float* recovery = out + (size_t)BB * CC * TT;       // (B, T)

    cudaFuncSetAttribute(k_deform, cudaFuncAttributeMaxDynamicSharedMemorySize,
                         DEF_SMEM_FLOATS * (int)sizeof(float));
    cudaFuncSetAttribute(k_recover2, cudaFuncAttributeMaxDynamicSharedMemorySize,
                         REC_SMEM_FLOATS * (int)sizeof(float));

    prep_wfrag<<<(2 * 96 * 2 * 8 * 32 * 2 + 255) / 256, 256>>>(rp1_w);
    k_deform<<<dim3(TT / 128, BB), 128, DEF_SMEM_FLOATS * sizeof(float)>>>(
        x, ow, ob, mw, mb, wgt, deformed);
    k_recover2<<<512, 256, REC_SMEM_FLOATS * sizeof(float)>>>(
        deformed, rp1_b, rp2_w, rp2_b, recovery);
}

// round 14
// speedup vs baseline: 1.4333x; 1.2158x over previous
#include <cuda_runtime.h>
#include <cuda_bf16.h>
#include <math.h>

#define BB 16
#define CC 256
#define TT 4096
#define KK 5

#define WIN  166
#define WOFF 16

// ===========================================================================
// Precomputed B fragments (bf16 hi/lo, packed pairs) for mma.m16n8k16.row.col.
// Wf2 (as uint2): index (((p*48 + kc)*2 + wn)*8 + nt)*32 + lane
//   .x = {W_p[n][k+1], W_p[n][k]}   (k = kc*16 + 2*tig)
//   .y = {W_p[n][k+9], W_p[n][k+8]}
// n = wn*64 + nt*8 + (lane>>2), tig = lane&3. p: 0=hi, 1=lo (bf16 split).
// ===========================================================================
__device__ __align__(16) unsigned g_wfrag[2 * 48 * 2 * 8 * 32 * 2];

__device__ __forceinline__ unsigned short bf16bits(float v) {
    return (unsigned short)(__bfloat16_as_ushort(__float2bfloat16_rn(v)));
}

__global__ void prep_wfrag(const float* __restrict__ rp1_w) {
    int e = blockIdx.x * blockDim.x + threadIdx.x;
    if (e >= 2 * 48 * 2 * 8 * 32 * 2) return;
    int r2   = e & 1;
    int lane = (e >> 1) & 31;
    int nt   = (e >> 6) & 7;
    int wn   = (e >> 9) & 1;
    int kc   = (e >> 10) % 48;
    int p    = (e >> 10) / 48;
    int tig = lane & 3;
    int g   = lane >> 2;
    int n = wn * 64 + nt * 8 + g;
    int k = kc * 16 + 2 * tig + r2 * 8;          // pair (k, k+1)
    unsigned out = 0;
    #pragma unroll
    for (int q = 0; q < 2; q++) {
        int kk = k + q;
        int c = kk / 3, d = kk - 3 * c;
        float w = __ldg(rp1_w + (n * CC + c) * 3 + d);
        float hi = __bfloat162float(__float2bfloat16_rn(w));
        float val = p ? (w - hi) : hi;           // lo re-rounded to bf16 below
        out |= ((unsigned)bf16bits(val)) << (16 * q);
    }
    g_wfrag[e] = out;
}

// m16n8k16 bf16 mma (family-portable PTX, sm_80+)
__device__ __forceinline__ void mma16(float* d, const unsigned* a, unsigned b0, unsigned b1) {
    asm volatile(
        "mma.sync.aligned.m16n8k16.row.col.f32.bf16.bf16.f32 "
        "{%0,%1,%2,%3},{%4,%5,%6,%7},{%8,%9},{%0,%1,%2,%3};"
        : "+f"(d[0]), "+f"(d[1]), "+f"(d[2]), "+f"(d[3])
        : "r"(a[0]), "r"(a[1]), "r"(a[2]), "r"(a[3]), "r"(b0), "r"(b1));
}

// pack two bf16-representable floats: low half = k-even element
__device__ __forceinline__ unsigned packbf2(float lo_elem, float hi_elem) {
    unsigned r;
    asm("cvt.rn.bf16x2.f32 %0, %1, %2;" : "=r"(r) : "f"(hi_elem), "f"(lo_elem));
    return r;
}

// ===========================================================================
// Kernel 1: round-7 k_deform VERBATIM (176.3us measured; numerics frozen)
// ===========================================================================
#define DEF_SMEM_FLOATS (CC * 30 + CC * KK + 32 * WIN)

__global__ __launch_bounds__(128) void k_deform(
    const float* __restrict__ x,
    const float* __restrict__ ow, const float* __restrict__ ob,
    const float* __restrict__ mw, const float* __restrict__ mb,
    const float* __restrict__ weight,
    float* __restrict__ deformed)
{
    extern __shared__ float dsm_d[];
    float* s_w  = dsm_d;
    float* s_dw = dsm_d + CC * 30;
    float* s_b  = dsm_d + CC * 30 + CC * KK;

    const int tid = threadIdx.x;
    const int t0 = blockIdx.x * 128;
    const int b = blockIdx.y;
    const float* xb = x + (size_t)b * CC * TT;

    for (int i = tid; i < CC * 30; i += 128) {
        int c = i / 30;
        int j = i - c * 30;
        float v;
        if (j < 15) {
            int k = j / 3, d = j - k * 3;
            v = ow[k * (CC * 3) + c * 3 + d];
        } else {
            int jj = j - 15;
            int k = jj / 3, d = jj - k * 3;
            v = mw[k * (CC * 3) + c * 3 + d];
        }
        s_w[i] = v;
    }

    float offa[KK] = {0.f, 0.f, 0.f, 0.f, 0.f};
    float moda[KK] = {0.f, 0.f, 0.f, 0.f, 0.f};

    for (int cc = 0; cc < CC; cc += 32) {
        __syncthreads();
        for (int idx = tid; idx < 32 * WIN; idx += 128) {
            int ci = idx / WIN;
            int u = idx - ci * WIN;
            int tg = t0 - WOFF + u;
            s_b[idx] = (tg >= 0 && tg < TT) ? __ldg(xb + (size_t)(cc + ci) * TT + tg) : 0.f;
        }
        __syncthreads();
        float offc[KK] = {0.f, 0.f, 0.f, 0.f, 0.f};
        float modc[KK] = {0.f, 0.f, 0.f, 0.f, 0.f};
        #pragma unroll 1
        for (int ci = 0; ci < 32; ci++) {
            const float* wrow = s_w + (cc + ci) * 30;
            const float* xs = s_b + ci * WIN + tid + (WOFF - 1);
            float x0 = xs[0];
            float x1 = xs[1];
            float x2 = xs[2];
            #pragma unroll
            for (int k = 0; k < KK; k++) {
                offc[k] += x0 * wrow[k * 3 + 0] + x1 * wrow[k * 3 + 1] + x2 * wrow[k * 3 + 2];
                modc[k] += x0 * wrow[15 + k * 3 + 0] + x1 * wrow[15 + k * 3 + 1] + x2 * wrow[15 + k * 3 + 2];
            }
        }
        #pragma unroll
        for (int k = 0; k < KK; k++) { offa[k] += offc[k]; moda[k] += modc[k]; }
    }

    const int t = t0 + tid;
    float mf[KK], mc[KK];
    int pfi[KK], pci[KK];
    #pragma unroll
    for (int k = 0; k < KK; k++) {
        float off = offa[k] + __ldg(ob + k);
        float z = moda[k] + __ldg(mb + k);
        float mod = 1.f / (1.f + expf(-z));
        float pos = (float)(t + k - 2) + off;
        pos = fminf(fmaxf(pos, 0.f), (float)(TT - 1));
        float pf = floorf(pos);
        float pc = ceilf(pos);
        mf[k] = (pc - pos) * mod;
        mc[k] = (pos - pf) * mod;
        pfi[k] = (int)pf;
        pci[k] = (int)pc;
    }

    int idxf[KK], idxc[KK];
    bool allin = true;
    #pragma unroll
    for (int k = 0; k < KK; k++) {
        idxf[k] = pfi[k] - (t0 - WOFF);
        idxc[k] = pci[k] - (t0 - WOFF);
        allin = allin && ((unsigned)idxf[k] < (unsigned)WIN) && ((unsigned)idxc[k] < (unsigned)WIN);
    }
    const bool fast = __all_sync(0xffffffffu, allin);

    __syncthreads();
    for (int i = tid; i < CC * KK; i += 128) {
        int c = i / KK;
        int k = i - c * KK;
        s_dw[i] = __ldg(weight + ((size_t)c * CC + c) * KK + k);
    }

    float* db = deformed + (size_t)b * CC * TT;
    for (int cc = 0; cc < CC; cc += 32) {
        __syncthreads();
        for (int idx = tid; idx < 32 * WIN; idx += 128) {
            int ci = idx / WIN;
            int u = idx - ci * WIN;
            int tg = t0 - WOFF + u;
            s_b[idx] = (tg >= 0 && tg < TT) ? __ldg(xb + (size_t)(cc + ci) * TT + tg) : 0.f;
        }
        __syncthreads();
        if (fast) {
            #pragma unroll 2
            for (int ci = 0; ci < 32; ci++) {
                const float* xs = s_b + ci * WIN;
                const float* dwc = s_dw + (cc + ci) * KK;
                float acc = 0.f;
                #pragma unroll
                for (int k = 0; k < KK; k++) {
                    float s = xs[idxf[k]] * mf[k] + xs[idxc[k]] * mc[k];
                    acc = fmaf(s, dwc[k], acc);
                }
                db[(size_t)(cc + ci) * TT + t] = acc;
            }
        } else {
            #pragma unroll 1
            for (int ci = 0; ci < 32; ci++) {
                const float* xc = xb + (size_t)(cc + ci) * TT;
                const float* dwc = s_dw + (cc + ci) * KK;
                float acc = 0.f;
                #pragma unroll
                for (int k = 0; k < KK; k++) {
                    float s = __ldg(xc + pfi[k]) * mf[k] + __ldg(xc + pci[k]) * mc[k];
                    acc = fmaf(s, dwc[k], acc);
                }
                db[(size_t)(cc + ci) * TT + t] = acc;
            }
        }
    }
}

// ===========================================================================
// Kernel 2: 3x-bf16 split GEMM via mma.m16n8k16 (h = ahi*bhi + ahi*blo +
// alo*bhi; omitted lo*lo ~ 2^-16 relative). A pre-split into smem bf16-exact
// fp32 hi/lo at staging. CTA: 256 threads = 128 t x 128 c2; grid 512.
// ===========================================================================
#define REC_SMEM_FLOATS (2 * 64 * 132)

__global__ __launch_bounds__(256, 2) void k_recover2(
    const float* __restrict__ deformed,
    const float* __restrict__ rp1_b,
    const float* __restrict__ rp2_w,
    const float* __restrict__ rp2_b,
    float* __restrict__ recovery)
{
    extern __shared__ float dsm_r[];
    float* shi = dsm_r;              // [j][u] bf16-hi part (stride 132)
    float* slo = dsm_r + 64 * 132;   // [j][u] bf16-lo part
    __shared__ float sp[2][128];

    const int tid = threadIdx.x;
    const int wid = tid >> 5;
    const int lane = tid & 31;
    const int wm = wid & 3;
    const int wn = wid >> 2;
    const int tig = lane & 3;
    const int g = lane >> 2;

    const int bx = blockIdx.x;
    const int b  = bx >> 5;
    const int t0 = (bx & 31) << 7;
    const float* db = deformed + (size_t)b * CC * TT;
    const uint2* Wf2 = reinterpret_cast<const uint2*>(g_wfrag);

    float dacc[2][8][4];
    #pragma unroll
    for (int mt = 0; mt < 2; mt++)
        #pragma unroll
        for (int nt = 0; nt < 8; nt++)
            #pragma unroll
            for (int r = 0; r < 4; r++) dacc[mt][nt][r] = 0.f;

    const int ttb = wm * 32 + g;

    for (int cg = 0; cg < 4; cg++) {
        __syncthreads();
        for (int i = tid; i < 64 * 130; i += 256) {
            int j = i / 130;
            int u = i - j * 130;
            int tg = t0 - 1 + u;
            float v = (tg >= 0 && tg < TT)
                ? __ldg(db + (size_t)(cg * 64 + j) * TT + tg) : 0.f;
            float hi = __bfloat162float(__float2bfloat16_rn(v));
            shi[j * 132 + u] = hi;
            slo[j * 132 + u] = __bfloat162float(__float2bfloat16_rn(v - hi));
        }
        __syncthreads();

        #pragma unroll 2
        for (int kcl = 0; kcl < 12; kcl++) {
            const int kc = cg * 12 + kcl;          // global k16-chunk
            const int kb = kc * 16;
            // 4 k-columns this thread touches: kb+2tig, +1, +8, +9
            const int k0 = kb + 2 * tig;
            const int c0 = k0 / 3,        d0 = k0 - 3 * c0;
            const int c1 = (k0 + 1) / 3,  d1 = (k0 + 1) - 3 * c1;
            const int c2k = (k0 + 8) / 3, d2 = (k0 + 8) - 3 * c2k;
            const int c3 = (k0 + 9) / 3,  d3 = (k0 + 9) - 3 * c3;
            const int o0 = (c0 - cg * 64) * 132 + d0;
            const int o1 = (c1 - cg * 64) * 132 + d1;
            const int o2 = (c2k - cg * 64) * 132 + d2;
            const int o3 = (c3 - cg * 64) * 132 + d3;

            unsigned ahi[2][4], alo[2][4];
            #pragma unroll
            for (int mt = 0; mt < 2; mt++) {
                const int tt = ttb + mt * 16;       // row g of this m16 tile
                ahi[mt][0] = packbf2(shi[o0 + tt],     shi[o1 + tt]);
                ahi[mt][1] = packbf2(shi[o0 + tt + 8], shi[o1 + tt + 8]);
                ahi[mt][2] = packbf2(shi[o2 + tt],     shi[o3 + tt]);
                ahi[mt][3] = packbf2(shi[o2 + tt + 8], shi[o3 + tt + 8]);
                alo[mt][0] = packbf2(slo[o0 + tt],     slo[o1 + tt]);
                alo[mt][1] = packbf2(slo[o0 + tt + 8], slo[o1 + tt + 8]);
                alo[mt][2] = packbf2(slo[o2 + tt],     slo[o3 + tt]);
                alo[mt][3] = packbf2(slo[o2 + tt + 8], slo[o3 + tt + 8]);
            }

            const int fb = ((kc * 2 + wn) * 8) * 32 + lane;          // hi
            const int fl = (((48 + kc) * 2 + wn) * 8) * 32 + lane;   // lo
            #pragma unroll
            for (int nt = 0; nt < 8; nt++) {
                uint2 bh = __ldg(Wf2 + fb + nt * 32);
                uint2 bl = __ldg(Wf2 + fl + nt * 32);
                #pragma unroll
                for (int mt = 0; mt < 2; mt++) {
                    mma16(dacc[mt][nt], ahi[mt], bh.x, bh.y);
                    mma16(dacc[mt][nt], ahi[mt], bl.x, bl.y);
                    mma16(dacc[mt][nt], alo[mt], bh.x, bh.y);
                }
            }
        }
    }

    #pragma unroll
    for (int mt = 0; mt < 2; mt++) {
        float s0 = 0.f, s8 = 0.f;
        #pragma unroll
        for (int nt = 0; nt < 8; nt++) {
            int c2 = wn * 64 + nt * 8 + tig * 2;
            float b1a = __ldg(rp1_b + c2),     b1b = __ldg(rp1_b + c2 + 1);
            float w2a = __ldg(rp2_w + c2),     w2b = __ldg(rp2_w + c2 + 1);
            s0 += fmaxf(dacc[mt][nt][0] + b1a, 0.f) * w2a
                + fmaxf(dacc[mt][nt][1] + b1b, 0.f) * w2b;
            s8 += fmaxf(dacc[mt][nt][2] + b1a, 0.f) * w2a
                + fmaxf(dacc[mt][nt][3] + b1b, 0.f) * w2b;
        }
        s0 += __shfl_xor_sync(0xffffffffu, s0, 1);
        s0 += __shfl_xor_sync(0xffffffffu, s0, 2);
        s8 += __shfl_xor_sync(0xffffffffu, s8, 1);
        s8 += __shfl_xor_sync(0xffffffffu, s8, 2);
        if (tig == 0) {
            sp[wn][wm * 32 + mt * 16 + g] = s0;
            sp[wn][wm * 32 + mt * 16 + g + 8] = s8;
        }
    }
    __syncthreads();

    if (tid < 128) {
        recovery[(size_t)b * TT + t0 + tid] = sp[0][tid] + sp[1][tid] + __ldg(rp2_b);
    }
}

// ---------------------------------------------------------------------------
extern "C" void kernel_launch(void* const* d_in, const int* in_sizes, int n_in,
                              void* d_out, int out_size) {
    const float* x     = (const float*)d_in[0];
    const float* ow    = (const float*)d_in[1];
    const float* ob    = (const float*)d_in[2];
    const float* mw    = (const float*)d_in[3];
    const float* mb    = (const float*)d_in[4];
    const float* wgt   = (const float*)d_in[5];
    const float* rp1_w = (const float*)d_in[6];
    const float* rp1_b = (const float*)d_in[7];
    const float* rp2_w = (const float*)d_in[8];
    const float* rp2_b = (const float*)d_in[9];

    float* out = (float*)d_out;
    float* deformed = out;                              // (B, C, T)
    float* recovery = out + (size_t)BB * CC * TT;       // (B, T)

    cudaFuncSetAttribute(k_deform, cudaFuncAttributeMaxDynamicSharedMemorySize,
                         DEF_SMEM_FLOATS * (int)sizeof(float));
    cudaFuncSetAttribute(k_recover2, cudaFuncAttributeMaxDynamicSharedMemorySize,
                         REC_SMEM_FLOATS * (int)sizeof(float));

    prep_wfrag<<<(2 * 48 * 2 * 8 * 32 * 2 + 255) / 256, 256>>>(rp1_w);
    k_deform<<<dim3(TT / 128, BB), 128, DEF_SMEM_FLOATS * sizeof(float)>>>(
        x, ow, ob, mw, mb, wgt, deformed);
    k_recover2<<<512, 256, REC_SMEM_FLOATS * sizeof(float)>>>(
        deformed, rp1_b, rp2_w, rp2_b, recovery);
}